// round 6
// baseline (speedup 1.0000x reference)
#include <cuda_runtime.h>
#include <cuda_bf16.h>
#include <math.h>
#include <stdint.h>

#define Bd 4
#define Td 2048
#define Cd 1024
#define Hd 16
#define DHd 64
#define Mtot (Bd * Td)      // 8192
#define K3 (3 * Cd)         // 3072 split-K: A=[hi|hi|lo], B=[hi|lo|hi]

typedef uint32_t u32;

// ---- scratch (__device__ globals; allocation-free rule) --------------------
__device__ float g_qkv[(size_t)Mtot * 3 * Cd];
__device__ __nv_bfloat16 g_x3[(size_t)Mtot * K3];
__device__ __nv_bfloat16 g_y3[(size_t)Mtot * K3];
__device__ __nv_bfloat16 g_wa3[(size_t)(3 * Cd) * K3];
__device__ __nv_bfloat16 g_wp3[(size_t)Cd * K3];
__device__ __nv_bfloat16 g_qhi[(size_t)Bd * Hd * Td * DHd];
__device__ __nv_bfloat16 g_qlo[(size_t)Bd * Hd * Td * DHd];
__device__ __nv_bfloat16 g_khi[(size_t)Bd * Hd * Td * DHd];
__device__ __nv_bfloat16 g_klo[(size_t)Bd * Hd * Td * DHd];
__device__ __nv_bfloat16 g_vthi[(size_t)Bd * Hd * DHd * Td];
__device__ __nv_bfloat16 g_vtlo[(size_t)Bd * Hd * DHd * Td];

// ---- helpers ----------------------------------------------------------------
__device__ __forceinline__ u32 smem_u32(const void* p) {
    u32 a;
    asm("{ .reg .u64 t; cvta.to.shared.u64 t, %1; cvt.u32.u64 %0, t; }" : "=r"(a) : "l"(p));
    return a;
}
__device__ __forceinline__ void ldm4(u32& r0, u32& r1, u32& r2, u32& r3, u32 addr) {
    asm volatile("ldmatrix.sync.aligned.m8n8.x4.shared.b16 {%0,%1,%2,%3}, [%4];"
                 : "=r"(r0), "=r"(r1), "=r"(r2), "=r"(r3) : "r"(addr));
}
__device__ __forceinline__ void mma16816(float* d, const u32* a, u32 b0, u32 b1) {
    asm volatile(
        "mma.sync.aligned.m16n8k16.row.col.f32.bf16.bf16.f32 "
        "{%0,%1,%2,%3}, {%4,%5,%6,%7}, {%8,%9}, {%0,%1,%2,%3};"
        : "+f"(d[0]), "+f"(d[1]), "+f"(d[2]), "+f"(d[3])
        : "r"(a[0]), "r"(a[1]), "r"(a[2]), "r"(a[3]), "r"(b0), "r"(b1));
}
__device__ __forceinline__ void cpa16(u32 dst, const void* src) {
    asm volatile("cp.async.cg.shared.global [%0], [%1], 16;" :: "r"(dst), "l"(src) : "memory");
}
__device__ __forceinline__ void cpa_commit() {
    asm volatile("cp.async.commit_group;" ::: "memory");
}
__device__ __forceinline__ u32 cvt_bf16x2(float hi, float lo) {
    u32 r;
    asm("cvt.rn.bf16x2.f32 %0, %1, %2;" : "=r"(r) : "f"(hi), "f"(lo));
    return r;
}
__device__ __forceinline__ float bf_lo(u32 r) { return __uint_as_float(r << 16); }
__device__ __forceinline__ float bf_hi(u32 r) { return __uint_as_float(r & 0xFFFF0000u); }

// FFMA-only exp (rel err ~1e-7), valid for x <= 0
__device__ __forceinline__ float fexp(float x) {
    x = fmaxf(x, -80.f);
    float t  = fmaf(x, 1.4426950408889634f, 12582912.0f);
    float fi = t - 12582912.0f;
    float f  = fmaf(x, 1.4426950408889634f, -fi);
    float p  = 0.00015403530393381609f;
    p = fmaf(p, f, 0.0013333558146428443f);
    p = fmaf(p, f, 0.009618129107628477f);
    p = fmaf(p, f, 0.05550410866482158f);
    p = fmaf(p, f, 0.2402265069591007f);
    p = fmaf(p, f, 0.6931471805599453f);
    p = fmaf(p, f, 1.0f);
    int ei = __float_as_int(t) - 0x4B400000;
    return __uint_as_float(__float_as_int(p) + (ei << 23));
}

// ---------------------------------------------------------------------------
// fp32 -> bf16x3 split conversions
// ---------------------------------------------------------------------------
__global__ void split_rows3(const float* __restrict__ in, __nv_bfloat16* __restrict__ out,
                            int R, int Cc)
{
    int idx = blockIdx.x * blockDim.x + threadIdx.x;
    int total = R * Cc / 4;
    if (idx >= total) return;
    int c = (idx % (Cc / 4)) * 4;
    int r = idx / (Cc / 4);
    float4 v = *(const float4*)(in + (size_t)r * Cc + c);
    __nv_bfloat162 h0 = __floats2bfloat162_rn(v.x, v.y);
    __nv_bfloat162 h1 = __floats2bfloat162_rn(v.z, v.w);
    __nv_bfloat162 l0 = __floats2bfloat162_rn(v.x - __bfloat162float(h0.x),
                                              v.y - __bfloat162float(h0.y));
    __nv_bfloat162 l1 = __floats2bfloat162_rn(v.z - __bfloat162float(h1.x),
                                              v.w - __bfloat162float(h1.y));
    __nv_bfloat16* o = out + (size_t)r * (3 * Cc) + c;
    uint2 hv = make_uint2(*(u32*)&h0, *(u32*)&h1);
    uint2 lv = make_uint2(*(u32*)&l0, *(u32*)&l1);
    *(uint2*)(o)          = hv;
    *(uint2*)(o + Cc)     = hv;
    *(uint2*)(o + 2 * Cc) = lv;
}

__global__ void __launch_bounds__(256) split_tr3(
    const float* __restrict__ w, __nv_bfloat16* __restrict__ out, int K, int N)
{
    __shared__ float tile[32][33];
    const int tid = threadIdx.x;
    const int n0 = blockIdx.x * 32, k0 = blockIdx.y * 32;
    {
        const int r = tid >> 3, c = (tid & 7) * 4;
        float4 v = *(const float4*)(w + (size_t)(k0 + r) * N + n0 + c);
        tile[r][c] = v.x; tile[r][c + 1] = v.y; tile[r][c + 2] = v.z; tile[r][c + 3] = v.w;
    }
    __syncthreads();
    {
        const int n = tid >> 3, c = (tid & 7) * 4;
        u32 hw[2], lw[2];
#pragma unroll
        for (int p = 0; p < 2; p++) {
            float v0 = tile[c + 2 * p][n], v1 = tile[c + 2 * p + 1][n];
            hw[p] = cvt_bf16x2(v1, v0);
            lw[p] = cvt_bf16x2(v1 - bf_hi(hw[p]), v0 - bf_lo(hw[p]));
        }
        __nv_bfloat16* o = out + (size_t)(n0 + n) * (3 * K) + k0 + c;
        *(uint2*)(o)         = make_uint2(hw[0], hw[1]);
        *(uint2*)(o + K)     = make_uint2(lw[0], lw[1]);
        *(uint2*)(o + 2 * K) = make_uint2(hw[0], hw[1]);
    }
}

// ---------------------------------------------------------------------------
// GEMM (HMMA) — unchanged from R5
// ---------------------------------------------------------------------------
#define GROWB 144
#define GBUFB (128 * GROWB)
__global__ void __launch_bounds__(128) gemm_mma(
    const __nv_bfloat16* __restrict__ A, const __nv_bfloat16* __restrict__ Bt,
    float* __restrict__ C, int Nout)
{
    extern __shared__ __align__(16) char sm[];
    const u32 sA = smem_u32(sm);
    const u32 sB = sA + 2 * GBUFB;

    const int tid = threadIdx.x, wid = tid >> 5, lane = tid & 31;
    const int wm = wid >> 1, wn = wid & 1;
    const int g = lane >> 2, t = lane & 3;
    const int row0 = blockIdx.y * 128, col0 = blockIdx.x * 128;

    const int lr = tid >> 3, lce = (tid & 7) * 8;
    const __nv_bfloat16* Ag = A + (size_t)(row0 + lr) * K3 + lce;
    const __nv_bfloat16* Bg = Bt + (size_t)(col0 + lr) * K3 + lce;
    const u32 da0 = sA + lr * GROWB + (tid & 7) * 16;
    const u32 db0 = sB + lr * GROWB + (tid & 7) * 16;

    float acc[4][8][4];
#pragma unroll
    for (int i = 0; i < 4; i++)
#pragma unroll
        for (int j = 0; j < 8; j++)
#pragma unroll
            for (int r = 0; r < 4; r++) acc[i][j][r] = 0.f;

    const int a_row_off = (64 * wm + (lane & 15)) * GROWB + ((lane >> 4) << 4);
    const int b_row_off = (64 * wn + (lane & 7) + 8 * ((lane >> 4) & 1)) * GROWB
                        + 16 * ((lane >> 3) & 1);

#pragma unroll
    for (int i = 0; i < 8; i++) {
        cpa16(da0 + i * 16 * GROWB, Ag + (size_t)(16 * i) * K3);
        cpa16(db0 + i * 16 * GROWB, Bg + (size_t)(16 * i) * K3);
    }
    cpa_commit();

    for (int kc = 0; kc < 48; kc++) {
        const int buf = kc & 1;
        if (kc < 47) {
            const int nb = buf ^ 1;
            const size_t ko = (size_t)(kc + 1) * 64;
#pragma unroll
            for (int i = 0; i < 8; i++) {
                cpa16(da0 + nb * GBUFB + i * 16 * GROWB, Ag + (size_t)(16 * i) * K3 + ko);
                cpa16(db0 + nb * GBUFB + i * 16 * GROWB, Bg + (size_t)(16 * i) * K3 + ko);
            }
            cpa_commit();
            asm volatile("cp.async.wait_group 1;" ::: "memory");
        } else {
            asm volatile("cp.async.wait_group 0;" ::: "memory");
        }
        __syncthreads();

        const u32 abase = sA + buf * GBUFB + a_row_off;
        const u32 bbase = sB + buf * GBUFB + b_row_off;
#pragma unroll
        for (int kt = 0; kt < 4; kt++) {
            u32 af[4][4], bf[4][4];
#pragma unroll
            for (int mt = 0; mt < 4; mt++)
                ldm4(af[mt][0], af[mt][1], af[mt][2], af[mt][3],
                     abase + mt * (16 * GROWB) + kt * 32);
#pragma unroll
            for (int np = 0; np < 4; np++)
                ldm4(bf[np][0], bf[np][1], bf[np][2], bf[np][3],
                     bbase + np * (16 * GROWB) + kt * 32);
#pragma unroll
            for (int mt = 0; mt < 4; mt++)
#pragma unroll
                for (int np = 0; np < 4; np++) {
                    mma16816(acc[mt][2 * np],     af[mt], bf[np][0], bf[np][1]);
                    mma16816(acc[mt][2 * np + 1], af[mt], bf[np][2], bf[np][3]);
                }
        }
        __syncthreads();
    }

#pragma unroll
    for (int mt = 0; mt < 4; mt++) {
        const int r0 = row0 + 64 * wm + 16 * mt + g;
#pragma unroll
        for (int nt = 0; nt < 8; nt++) {
            const int col = col0 + 64 * wn + 8 * nt + 2 * t;
            *(float2*)(C + (size_t)r0 * Nout + col)       = make_float2(acc[mt][nt][0], acc[mt][nt][1]);
            *(float2*)(C + (size_t)(r0 + 8) * Nout + col) = make_float2(acc[mt][nt][2], acc[mt][nt][3]);
        }
    }
}

// ---------------------------------------------------------------------------
// prep_attn — unchanged from R5
// ---------------------------------------------------------------------------
__global__ void __launch_bounds__(256) prep_attn(const float* __restrict__ qkv)
{
    __shared__ __nv_bfloat16 tvhi[64][72];
    __shared__ __nv_bfloat16 tvlo[64][72];
    const int tid = threadIdx.x;
    const int tb = blockIdx.x, bh = blockIdx.y;
    const int b = bh >> 4, h = bh & 15;

#pragma unroll
    for (int i = 0; i < 4; i++) {
        const int u = tid + 256 * i;
        const int tr = u >> 4;
        const int d4 = (u & 15) * 4;
        const int tg = tb * 64 + tr;
        const size_t base = ((size_t)(b * Td + tg)) * 3072 + h * 64 + d4;
        float4 q = *(const float4*)(qkv + base);
        float4 k = *(const float4*)(qkv + base + 1024);
        float4 v = *(const float4*)(qkv + base + 2048);
        q.x *= 0.125f; q.y *= 0.125f; q.z *= 0.125f; q.w *= 0.125f;

        const size_t qidx = ((size_t)bh * Td + tg) * 64 + d4;
        __nv_bfloat162 qh0 = __floats2bfloat162_rn(q.x, q.y);
        __nv_bfloat162 qh1 = __floats2bfloat162_rn(q.z, q.w);
        __nv_bfloat162 ql0 = __floats2bfloat162_rn(q.x - __bfloat162float(qh0.x), q.y - __bfloat162float(qh0.y));
        __nv_bfloat162 ql1 = __floats2bfloat162_rn(q.z - __bfloat162float(qh1.x), q.w - __bfloat162float(qh1.y));
        *(uint2*)(g_qhi + qidx) = make_uint2(*(u32*)&qh0, *(u32*)&qh1);
        *(uint2*)(g_qlo + qidx) = make_uint2(*(u32*)&ql0, *(u32*)&ql1);

        __nv_bfloat162 kh0 = __floats2bfloat162_rn(k.x, k.y);
        __nv_bfloat162 kh1 = __floats2bfloat162_rn(k.z, k.w);
        __nv_bfloat162 kl0 = __floats2bfloat162_rn(k.x - __bfloat162float(kh0.x), k.y - __bfloat162float(kh0.y));
        __nv_bfloat162 kl1 = __floats2bfloat162_rn(k.z - __bfloat162float(kh1.x), k.w - __bfloat162float(kh1.y));
        *(uint2*)(g_khi + qidx) = make_uint2(*(u32*)&kh0, *(u32*)&kh1);
        *(uint2*)(g_klo + qidx) = make_uint2(*(u32*)&kl0, *(u32*)&kl1);

        float vv[4] = {v.x, v.y, v.z, v.w};
#pragma unroll
        for (int j = 0; j < 4; j++) {
            __nv_bfloat16 hi = __float2bfloat16(vv[j]);
            __nv_bfloat16 lo = __float2bfloat16(vv[j] - __bfloat162float(hi));
            tvhi[d4 + j][tr] = hi;
            tvlo[d4 + j][tr] = lo;
        }
    }
    __syncthreads();
#pragma unroll
    for (int i = 0; i < 2; i++) {
        const int u = tid + 256 * i;
        const int d = u >> 3;
        const int tc = (u & 7) * 8;
        const size_t vidx = ((size_t)bh * 64 + d) * Td + tb * 64 + tc;
        *(uint4*)(g_vthi + vidx) = *(uint4*)&tvhi[d][tc];
        *(uint4*)(g_vtlo + vidx) = *(uint4*)&tvlo[d][tc];
    }
}

// ---------------------------------------------------------------------------
// flash_mma: q-tile 128 (4 warps x 32 q-rows, 2 m-frags/warp), k-tile 64.
// ---------------------------------------------------------------------------
__global__ void __launch_bounds__(128) flash_mma(__nv_bfloat16* __restrict__ y3)
{
    __shared__ __align__(16) __nv_bfloat16 s_t[4][64 * 72];
    const int tid = threadIdx.x, wid = tid >> 5, lane = tid & 31;
    const int g = lane >> 2, t = lane & 3;
    const int qt = gridDim.x - 1 - blockIdx.x;   // heavy q-tiles first
    const int bh = blockIdx.y;
    const int b = bh >> 4, h = bh & 15;

    const size_t qkbase = (size_t)bh * Td * 64;
    const size_t vtbase = (size_t)bh * 64 * Td;

    const u32 s0 = smem_u32(s_t);
    const u32 sKhi = s0, sKlo = s0 + 9216, sVhi = s0 + 18432, sVlo = s0 + 27648;

    const int b_off = ((lane & 7) + 8 * ((lane >> 4) & 1)) * 144 + 16 * ((lane >> 3) & 1);

    // ---- stage Q tile (128x64 hi at s0, lo at s0+18432), ldmatrix to regs ----
    {
        __nv_bfloat16* sq  = &s_t[0][0];
        __nv_bfloat16* sql = &s_t[2][0];
#pragma unroll
        for (int i = 0; i < 8; i++) {
            const int u = tid + 128 * i;        // 0..1023
            const int r = u >> 3, c = (u & 7) * 8;
            const size_t gq = qkbase + (size_t)(qt * 128 + r) * 64 + c;
            *(uint4*)(sq + r * 72 + c)  = *(const uint4*)(g_qhi + gq);
            *(uint4*)(sql + r * 72 + c) = *(const uint4*)(g_qlo + gq);
        }
    }
    __syncthreads();
    u32 qh[2][4][4], ql[2][4][4];
#pragma unroll
    for (int mf = 0; mf < 2; mf++) {
        const int a_off = (32 * wid + 16 * mf + (lane & 15)) * 144 + ((lane >> 4) << 4);
#pragma unroll
        for (int kt = 0; kt < 4; kt++) {
            ldm4(qh[mf][kt][0], qh[mf][kt][1], qh[mf][kt][2], qh[mf][kt][3],
                 s0 + a_off + kt * 32);
            ldm4(ql[mf][kt][0], ql[mf][kt][1], ql[mf][kt][2], ql[mf][kt][3],
                 s0 + 18432 + a_off + kt * 32);
        }
    }

    float o[2][8][4];
#pragma unroll
    for (int mf = 0; mf < 2; mf++)
#pragma unroll
        for (int j = 0; j < 8; j++)
#pragma unroll
            for (int r = 0; r < 4; r++) o[mf][j][r] = 0.f;
    float m[2][2] = {{-1e30f, -1e30f}, {-1e30f, -1e30f}};
    float l[2][2] = {{0.f, 0.f}, {0.f, 0.f}};

    const int kb_end = 2 * qt + 1;
    for (int kb = 0; kb <= kb_end; kb++) {
        __syncthreads();
#pragma unroll
        for (int i = 0; i < 4; i++) {
            const int u = tid + 128 * i;
            const int r = u >> 3, c = (u & 7) * 8;
            const size_t gk = qkbase + (size_t)(kb * 64 + r) * 64 + c;
            const size_t gv = vtbase + (size_t)r * Td + kb * 64 + c;
            *(uint4*)&s_t[0][r * 72 + c] = *(const uint4*)(g_khi + gk);
            *(uint4*)&s_t[1][r * 72 + c] = *(const uint4*)(g_klo + gk);
            *(uint4*)&s_t[2][r * 72 + c] = *(const uint4*)(g_vthi + gv);
            *(uint4*)&s_t[3][r * 72 + c] = *(const uint4*)(g_vtlo + gv);
        }
        __syncthreads();

        // ---- S = Qhi*Khi + Qlo*Khi + Qhi*Klo, both m-frags ----
        float s[2][8][4];
#pragma unroll
        for (int mf = 0; mf < 2; mf++)
#pragma unroll
            for (int j = 0; j < 8; j++)
#pragma unroll
                for (int r = 0; r < 4; r++) s[mf][j][r] = 0.f;
#pragma unroll
        for (int np = 0; np < 4; np++) {
#pragma unroll
            for (int kt = 0; kt < 4; kt++) {
                const int off = b_off + np * (16 * 144) + kt * 32;
                u32 h0, h1, h2, h3, e0, e1, e2, e3;
                ldm4(h0, h1, h2, h3, sKhi + off);
                mma16816(s[0][2 * np],     qh[0][kt], h0, h1);
                mma16816(s[0][2 * np + 1], qh[0][kt], h2, h3);
                mma16816(s[1][2 * np],     qh[1][kt], h0, h1);
                mma16816(s[1][2 * np + 1], qh[1][kt], h2, h3);
                mma16816(s[0][2 * np],     ql[0][kt], h0, h1);
                mma16816(s[0][2 * np + 1], ql[0][kt], h2, h3);
                mma16816(s[1][2 * np],     ql[1][kt], h0, h1);
                mma16816(s[1][2 * np + 1], ql[1][kt], h2, h3);
                ldm4(e0, e1, e2, e3, sKlo + off);
                mma16816(s[0][2 * np],     qh[0][kt], e0, e1);
                mma16816(s[0][2 * np + 1], qh[0][kt], e2, e3);
                mma16816(s[1][2 * np],     qh[1][kt], e0, e1);
                mma16816(s[1][2 * np + 1], qh[1][kt], e2, e3);
            }
        }

        // ---- causal mask (only last two k-tiles can cross the diagonal) ----
        if (kb >= 2 * qt) {
#pragma unroll
            for (int mf = 0; mf < 2; mf++) {
                const int qg0 = qt * 128 + 32 * wid + 16 * mf + g;
                const int qg1 = qg0 + 8;
#pragma unroll
                for (int nt = 0; nt < 8; nt++) {
                    const int kg = kb * 64 + 8 * nt + 2 * t;
                    if (kg > qg0)     s[mf][nt][0] = -1e30f;
                    if (kg + 1 > qg0) s[mf][nt][1] = -1e30f;
                    if (kg > qg1)     s[mf][nt][2] = -1e30f;
                    if (kg + 1 > qg1) s[mf][nt][3] = -1e30f;
                }
            }
        }

        // ---- online softmax ----
#pragma unroll
        for (int mf = 0; mf < 2; mf++) {
            float ml0 = -1e30f, ml1 = -1e30f;
#pragma unroll
            for (int nt = 0; nt < 8; nt++) {
                ml0 = fmaxf(ml0, fmaxf(s[mf][nt][0], s[mf][nt][1]));
                ml1 = fmaxf(ml1, fmaxf(s[mf][nt][2], s[mf][nt][3]));
            }
            ml0 = fmaxf(ml0, __shfl_xor_sync(0xffffffffu, ml0, 1));
            ml0 = fmaxf(ml0, __shfl_xor_sync(0xffffffffu, ml0, 2));
            ml1 = fmaxf(ml1, __shfl_xor_sync(0xffffffffu, ml1, 1));
            ml1 = fmaxf(ml1, __shfl_xor_sync(0xffffffffu, ml1, 2));
            const float mn0 = fmaxf(m[mf][0], ml0), mn1 = fmaxf(m[mf][1], ml1);
            const float cr0 = fexp(m[mf][0] - mn0), cr1 = fexp(m[mf][1] - mn1);
            m[mf][0] = mn0; m[mf][1] = mn1;
            float ls0 = 0.f, ls1 = 0.f;
#pragma unroll
            for (int nt = 0; nt < 8; nt++) {
                s[mf][nt][0] = fexp(s[mf][nt][0] - mn0); ls0 += s[mf][nt][0];
                s[mf][nt][1] = fexp(s[mf][nt][1] - mn0); ls0 += s[mf][nt][1];
                s[mf][nt][2] = fexp(s[mf][nt][2] - mn1); ls1 += s[mf][nt][2];
                s[mf][nt][3] = fexp(s[mf][nt][3] - mn1); ls1 += s[mf][nt][3];
            }
            ls0 += __shfl_xor_sync(0xffffffffu, ls0, 1);
            ls0 += __shfl_xor_sync(0xffffffffu, ls0, 2);
            ls1 += __shfl_xor_sync(0xffffffffu, ls1, 1);
            ls1 += __shfl_xor_sync(0xffffffffu, ls1, 2);
            l[mf][0] = l[mf][0] * cr0 + ls0;
            l[mf][1] = l[mf][1] * cr1 + ls1;
#pragma unroll
            for (int j = 0; j < 8; j++) {
                o[mf][j][0] *= cr0; o[mf][j][1] *= cr0;
                o[mf][j][2] *= cr1; o[mf][j][3] *= cr1;
            }
        }

        // ---- O += Phi*Vhi + Plo*Vhi + Phi*Vlo ----
#pragma unroll
        for (int kt = 0; kt < 4; kt++) {
            u32 ph[2][4], pl[2][4];
#pragma unroll
            for (int mf = 0; mf < 2; mf++) {
                ph[mf][0] = cvt_bf16x2(s[mf][2 * kt][1],     s[mf][2 * kt][0]);
                ph[mf][1] = cvt_bf16x2(s[mf][2 * kt][3],     s[mf][2 * kt][2]);
                ph[mf][2] = cvt_bf16x2(s[mf][2 * kt + 1][1], s[mf][2 * kt + 1][0]);
                ph[mf][3] = cvt_bf16x2(s[mf][2 * kt + 1][3], s[mf][2 * kt + 1][2]);
                pl[mf][0] = cvt_bf16x2(s[mf][2 * kt][1] - bf_hi(ph[mf][0]),
                                       s[mf][2 * kt][0] - bf_lo(ph[mf][0]));
                pl[mf][1] = cvt_bf16x2(s[mf][2 * kt][3] - bf_hi(ph[mf][1]),
                                       s[mf][2 * kt][2] - bf_lo(ph[mf][1]));
                pl[mf][2] = cvt_bf16x2(s[mf][2 * kt + 1][1] - bf_hi(ph[mf][2]),
                                       s[mf][2 * kt + 1][0] - bf_lo(ph[mf][2]));
                pl[mf][3] = cvt_bf16x2(s[mf][2 * kt + 1][3] - bf_hi(ph[mf][3]),
                                       s[mf][2 * kt + 1][2] - bf_lo(ph[mf][3]));
            }
#pragma unroll
            for (int np = 0; np < 4; np++) {
                const int off = b_off + np * (16 * 144) + kt * 32;
                u32 v0, v1, v2, v3, w0, w1, w2, w3;
                ldm4(v0, v1, v2, v3, sVhi + off);
                mma16816(o[0][2 * np],     ph[0], v0, v1);
                mma16816(o[0][2 * np + 1], ph[0], v2, v3);
                mma16816(o[1][2 * np],     ph[1], v0, v1);
                mma16816(o[1][2 * np + 1], ph[1], v2, v3);
                mma16816(o[0][2 * np],     pl[0], v0, v1);
                mma16816(o[0][2 * np + 1], pl[0], v2, v3);
                mma16816(o[1][2 * np],     pl[1], v0, v1);
                mma16816(o[1][2 * np + 1], pl[1], v2, v3);
                ldm4(w0, w1, w2, w3, sVlo + off);
                mma16816(o[0][2 * np],     ph[0], w0, w1);
                mma16816(o[0][2 * np + 1], ph[0], w2, w3);
                mma16816(o[1][2 * np],     ph[1], w0, w1);
                mma16816(o[1][2 * np + 1], ph[1], w2, w3);
            }
        }
    }

    // ---- epilogue ----
#pragma unroll
    for (int mf = 0; mf < 2; mf++) {
        const float inv0 = 1.f / l[mf][0], inv1 = 1.f / l[mf][1];
        const int tg0 = qt * 128 + 32 * wid + 16 * mf + g;
        const size_t m0i = (size_t)(b * Td + tg0) * K3;
        const size_t m1i = (size_t)(b * Td + tg0 + 8) * K3;
#pragma unroll
        for (int nt = 0; nt < 8; nt++) {
            const int col = h * 64 + 8 * nt + 2 * t;
            {
                const float f0 = o[mf][nt][0] * inv0, f1 = o[mf][nt][1] * inv0;
                const u32 hi = cvt_bf16x2(f1, f0);
                const u32 lo = cvt_bf16x2(f1 - bf_hi(hi), f0 - bf_lo(hi));
                *(u32*)(y3 + m0i + col)        = hi;
                *(u32*)(y3 + m0i + col + 1024) = hi;
                *(u32*)(y3 + m0i + col + 2048) = lo;
            }
            {
                const float f2 = o[mf][nt][2] * inv1, f3 = o[mf][nt][3] * inv1;
                const u32 hi = cvt_bf16x2(f3, f2);
                const u32 lo = cvt_bf16x2(f3 - bf_hi(hi), f2 - bf_lo(hi));
                *(u32*)(y3 + m1i + col)        = hi;
                *(u32*)(y3 + m1i + col + 1024) = hi;
                *(u32*)(y3 + m1i + col + 2048) = lo;
            }
        }
    }
}

// ---------------------------------------------------------------------------
extern "C" void kernel_launch(void* const* d_in, const int* in_sizes, int n_in,
                              void* d_out, int out_size)
{
    const float* x      = (const float*)d_in[0];
    const float* w_attn = (const float*)d_in[1];
    const float* w_proj = (const float*)d_in[2];
    float* out = (float*)d_out;

    float* qkv;
    __nv_bfloat16 *x3, *y3, *wa3, *wp3;
    cudaGetSymbolAddress((void**)&qkv, g_qkv);
    cudaGetSymbolAddress((void**)&x3, g_x3);
    cudaGetSymbolAddress((void**)&y3, g_y3);
    cudaGetSymbolAddress((void**)&wa3, g_wa3);
    cudaGetSymbolAddress((void**)&wp3, g_wp3);

    const int gemm_smem = 4 * GBUFB;   // 73728 B
    cudaFuncSetAttribute(gemm_mma, cudaFuncAttributeMaxDynamicSharedMemorySize, gemm_smem);

    split_rows3<<<(Mtot * Cd / 4 + 255) / 256, 256>>>(x, x3, Mtot, Cd);
    split_tr3<<<dim3(3 * Cd / 32, Cd / 32), 256>>>(w_attn, wa3, Cd, 3 * Cd);
    split_tr3<<<dim3(Cd / 32, Cd / 32), 256>>>(w_proj, wp3, Cd, Cd);

    dim3 g1(3 * Cd / 128, Mtot / 128);    // (24, 64)
    gemm_mma<<<g1, 128, gemm_smem>>>(x3, wa3, qkv, 3 * Cd);

    dim3 gp(Td / 64, Bd * Hd);
    prep_attn<<<gp, 256>>>(qkv);

    dim3 g2(Td / 128, Bd * Hd);           // (16, 64)
    flash_mma<<<g2, 128>>>(y3);

    dim3 g3(Cd / 128, Mtot / 128);        // (8, 64)
    gemm_mma<<<g3, 128, gemm_smem>>>(y3, wp3, out, Cd);
}